// round 9
// baseline (speedup 1.0000x reference)
#include <cuda_runtime.h>
#include <cuda_bf16.h>
#include <math.h>
#include <stdint.h>

#define B_SZ 64
#define T_SZ 64
#define NI 2048
#define NH 2048
#define MBK 4
#define MN 128
#define MW 20
#define M_ROWS 4096
#define KW 4096   // compact split width [hi | lo]
#define KX 6144   // logical K (3 terms x 2048)

// ---------------- device scratch (t-major rows: r = t*64 + b) ----------------
__device__ float g_pre[(size_t)M_ROWS * NH];
__device__ float g_bpre[NH];
__device__ __nv_bfloat16 g_Ax[(size_t)M_ROWS * KW];   // x split
__device__ __nv_bfloat16 g_Ah[(size_t)M_ROWS * KW];   // H split
__device__ __nv_bfloat16 g_B0[(size_t)NH * KW];       // W_in^T  [hi|lo]
__device__ __nv_bfloat16 g_B1[(size_t)NH * KW];       // W_out^T [hi|lo]
// progress flags (zeroed every launch by init_flags)
__device__ int g_prog[64];     // per step: 128 half-block arrivals
__device__ int g_kflag[128];   // per (b, half): last completed step + 1
__device__ float g_kpart[128 * MW];

// ---------------- helpers ----------------------------------------------------
__device__ __forceinline__ uint32_t s2u(const void* p) {
    uint32_t r;
    asm("{ .reg .u64 t; cvta.to.shared.u64 t, %1; cvt.u32.u64 %0, t; }"
        : "=r"(r) : "l"(p));
    return r;
}
#define SWZ(x) ((x) ^ (((x) >> 3) & 0x70))
__device__ __forceinline__ void cpa16(uint32_t s, const void* g) {
    asm volatile("cp.async.cg.shared.global [%0], [%1], 16;" :: "r"(s), "l"(g)
                 : "memory");
}
#define CP_COMMIT asm volatile("cp.async.commit_group;" ::: "memory")
__device__ __forceinline__ void cp_wait1() {
    asm volatile("cp.async.wait_group 1;" ::: "memory");
}
__device__ __forceinline__ void cp_wait0() {
    asm volatile("cp.async.wait_group 0;" ::: "memory");
}
__device__ __forceinline__ void ldsm4(uint32_t* r, uint32_t a) {
    asm volatile("ldmatrix.sync.aligned.m8n8.x4.shared.b16 {%0,%1,%2,%3}, [%4];"
                 : "=r"(r[0]), "=r"(r[1]), "=r"(r[2]), "=r"(r[3]) : "r"(a));
}
__device__ __forceinline__ void mma16816(float* c, const uint32_t* a,
                                         const uint32_t* b) {
    asm volatile(
        "mma.sync.aligned.m16n8k16.row.col.f32.bf16.bf16.f32 "
        "{%0,%1,%2,%3}, {%4,%5,%6,%7}, {%8,%9}, {%0,%1,%2,%3};"
        : "+f"(c[0]), "+f"(c[1]), "+f"(c[2]), "+f"(c[3])
        : "r"(a[0]), "r"(a[1]), "r"(a[2]), "r"(a[3]), "r"(b[0]), "r"(b[1]));
}

// ---------------- small prep kernels -----------------------------------------
__global__ void init_flags() {
    int i = threadIdx.x;
    if (i < 64) g_prog[i] = 0;
    if (i < 128) g_kflag[i] = 0;
}

__global__ void conv_x(const float4* __restrict__ x4) {
    int i = blockIdx.x * 256 + threadIdx.x;
    if (i >= M_ROWS * NI / 4) return;
    int row = i >> 9, c4 = i & 511;          // input row = b*64 + t
    int b = row >> 6, t = row & 63;
    int orow = t * 64 + b;                   // t-major
    float4 v = x4[i];
    __nv_bfloat16 hx = __float2bfloat16(v.x), hy = __float2bfloat16(v.y);
    __nv_bfloat16 hz = __float2bfloat16(v.z), hw = __float2bfloat16(v.w);
    __nv_bfloat162* p = (__nv_bfloat162*)(g_Ax + (size_t)orow * KW);
    p[2 * c4] = __halves2bfloat162(hx, hy);
    p[2 * c4 + 1] = __halves2bfloat162(hz, hw);
    p[1024 + 2 * c4] = __halves2bfloat162(
        __float2bfloat16(v.x - __bfloat162float(hx)),
        __float2bfloat16(v.y - __bfloat162float(hy)));
    p[1024 + 2 * c4 + 1] = __halves2bfloat162(
        __float2bfloat16(v.z - __bfloat162float(hz)),
        __float2bfloat16(v.w - __bfloat162float(hw)));
}

__global__ void trans_split(const float* __restrict__ W,
                            __nv_bfloat16* __restrict__ T) {
    __shared__ float s[32][33];
    int n0 = blockIdx.x * 32, k0 = blockIdx.y * 32;
    int tx = threadIdx.x, ty = threadIdx.y;
#pragma unroll
    for (int i = 0; i < 32; i += 8)
        s[ty + i][tx] = W[(size_t)(k0 + ty + i) * NH + n0 + tx];
    __syncthreads();
#pragma unroll
    for (int i = 0; i < 32; i += 8) {
        float v = s[tx][ty + i];
        __nv_bfloat16 h = __float2bfloat16(v);
        __nv_bfloat16 l = __float2bfloat16(v - __bfloat162float(h));
        size_t o = (size_t)(n0 + ty + i) * KW + k0 + tx;
        T[o] = h;
        T[o + 2048] = l;
    }
}

__global__ void bias_comb(const float* __restrict__ a,
                          const float* __restrict__ b) {
    int i = blockIdx.x * 512 + threadIdx.x;
    if (i < NH) g_bpre[i] = a[i] + b[i];
}

// ---------------- GEMM body (device function) --------------------------------
#define BM 128
#define BN 128
#define BK 64
#define STG 3
#define STAGE_B 32768
#define NT (KX / BK)  // 96
#define GEMM_SMEM (STG * STAGE_B + 1024)  // 99328

template <int MODE>  // 0: C=g_pre (t-major) | 1: wait g_prog, C=out remap+clamp
__device__ void gemm_body(char* dsm, int cta,
                          const __nv_bfloat16* __restrict__ Ag,
                          const __nv_bfloat16* __restrict__ Bg,
                          const float* __restrict__ bias,
                          float* __restrict__ C) {
    const int by = cta >> 4, bx = cta & 15;
    const int tid = threadIdx.x, lane = tid & 31, wid = tid >> 5;
    const int wm = wid & 1, wn = wid >> 1;

    if (MODE == 1) {
        if (tid == 0) {
            volatile int* pr = g_prog;
            while (pr[2 * by] < 128 || pr[2 * by + 1] < 128) __nanosleep(256);
        }
        __syncthreads();
        __threadfence();
    }

    uint32_t base = (s2u(dsm) + 1023u) & ~1023u;
    const __nv_bfloat16* Abase = Ag + (size_t)(by * BM + (tid >> 3)) * KW +
                                 (tid & 7) * 8;
    const __nv_bfloat16* Bbase = Bg + (size_t)(bx * BN + (tid >> 3)) * KW +
                                 (tid & 7) * 8;

    float acc[4][4][4];
#pragma unroll
    for (int m = 0; m < 4; m++)
#pragma unroll
        for (int n = 0; n < 4; n++)
#pragma unroll
            for (int q = 0; q < 4; q++) acc[m][n][q] = 0.f;

    uint32_t stoff[4];
#pragma unroll
    for (int u = 0; u < 4; u++) {
        int unit = tid + 256 * u;
        stoff[u] = SWZ((uint32_t)((unit >> 3) * 128 + (unit & 7) * 16));
    }

    auto load_stage = [&](int s, int ks) {
        int ka = ((ks & 31) + ((ks >= 64) ? 32 : 0)) * 64;
        int kb = ((ks & 31) + (((ks >> 5) == 1) ? 32 : 0)) * 64;
        uint32_t sb = base + s * STAGE_B;
#pragma unroll
        for (int u = 0; u < 4; u++)
            cpa16(sb + stoff[u], Abase + (size_t)(32 * u) * KW + ka);
#pragma unroll
        for (int u = 0; u < 4; u++)
            cpa16(sb + 16384 + stoff[u], Bbase + (size_t)(32 * u) * KW + kb);
    };

    load_stage(0, 0);
    CP_COMMIT;
    load_stage(1, 1);
    CP_COMMIT;

    uint32_t aoff[4], boff[2];
#pragma unroll
    for (int mt = 0; mt < 4; mt++)
        aoff[mt] = (uint32_t)((wm * 64 + mt * 16 + (lane & 15)) * 128 +
                              (lane >> 4) * 16);
#pragma unroll
    for (int p = 0; p < 2; p++)
        boff[p] = (uint32_t)((wn * 32 + p * 16 + (lane & 15)) * 128 +
                             (lane >> 4) * 16);

    for (int ks = 0; ks < NT; ks++) {
        if (ks < NT - 1) cp_wait1();
        else cp_wait0();
        __syncthreads();
        if (ks + 2 < NT) {
            load_stage((ks + 2) % STG, ks + 2);
            CP_COMMIT;
        }
        const uint32_t sa = base + (ks % STG) * STAGE_B;
        const uint32_t sb = sa + 16384;
#pragma unroll
        for (int k16 = 0; k16 < 4; k16++) {
            uint32_t aF[4][4], bF[4][2];
#pragma unroll
            for (int mt = 0; mt < 4; mt++)
                ldsm4(aF[mt], sa + SWZ(aoff[mt] + k16 * 32));
#pragma unroll
            for (int p = 0; p < 2; p++) {
                uint32_t t[4];
                ldsm4(t, sb + SWZ(boff[p] + k16 * 32));
                bF[2 * p][0] = t[0];
                bF[2 * p][1] = t[2];
                bF[2 * p + 1][0] = t[1];
                bF[2 * p + 1][1] = t[3];
            }
#pragma unroll
            for (int mt = 0; mt < 4; mt++)
#pragma unroll
                for (int nt = 0; nt < 4; nt++)
                    mma16816(acc[mt][nt], aF[mt], bF[nt]);
        }
        __syncthreads();
    }

    const int g = lane >> 2, t4 = lane & 3;
#pragma unroll
    for (int mt = 0; mt < 4; mt++) {
        const int r0 = by * BM + wm * 64 + mt * 16 + g;
        size_t rowbase, rowbase8;
        if (MODE == 0) {
            rowbase = (size_t)r0 * NH;
            rowbase8 = (size_t)(r0 + 8) * NH;
        } else {
            rowbase = (size_t)((r0 & 63) * 64 + (r0 >> 6)) * NH;
            rowbase8 = (size_t)(((r0 + 8) & 63) * 64 + ((r0 + 8) >> 6)) * NH;
        }
#pragma unroll
        for (int nt = 0; nt < 4; nt++) {
            const int c0 = bx * BN + wn * 32 + nt * 8 + t4 * 2;
            float2 bb2 = *(const float2*)&bias[c0];
            float v0 = acc[mt][nt][0] + bb2.x, v1 = acc[mt][nt][1] + bb2.y;
            float v2 = acc[mt][nt][2] + bb2.x, v3 = acc[mt][nt][3] + bb2.y;
            if (MODE == 1) {
                v0 = fminf(fmaxf(v0, 0.f), 1.f);
                v1 = fminf(fmaxf(v1, 0.f), 1.f);
                v2 = fminf(fmaxf(v2, 0.f), 1.f);
                v3 = fminf(fmaxf(v3, 0.f), 1.f);
            }
            float2 w0 = {v0, v1}, w1 = {v2, v3};
            *(float2*)&C[rowbase + c0] = w0;
            *(float2*)&C[rowbase8 + c0] = w1;
        }
    }
}

__global__ void __launch_bounds__(256, 2)
gemm0_k() {
    extern __shared__ char dsm[];
    gemm_body<0>(dsm, blockIdx.x, g_Ax, g_B0, g_bpre, g_pre);
}

// ---------------- recurrence half-block (1024 hidden rows) -------------------
__device__ void recur_half(char* dsm, int b, int half,
                           const float* __restrict__ h0,
                           const float* __restrict__ b_key,
                           const float* __restrict__ W_read,
                           const float* __restrict__ memory,
                           const float* __restrict__ W_key) {
    float* rs = (float*)dsm;
    float* skey = rs;            // 1024*21 = 21504
    float* sh = rs + 21504;      // 1024
    float* spre = sh + 1024;     // 1024
    float* sbn = spre + 1024;    // 512
    float* sred = sbn + 512;     // 160
    float* skv = sred + 160;     // 32
    float* sprob = skv + 32;     // 128
    float* sr = sprob + 128;     // 32
    const uint32_t spre_u = s2u(spre);

    const int tid = threadIdx.x;
    const int lane = tid & 31, warp = tid >> 5;
    const int rowoff = half * 1024;
    const int self = b * 2 + half, peer = b * 2 + (half ^ 1);

    for (int i = tid; i < 1024; i += 256) sh[i] = h0[(size_t)b * NH + rowoff + i];
    for (int r = tid; r < 1024; r += 256) {
        const float* kr = W_key + (size_t)(rowoff + r) * MW;
#pragma unroll
        for (int j = 0; j < MW; j++) skey[r * 21 + j] = kr[j];
    }
    for (int i = tid; i < MBK * MN; i += 256) {
        float s = 0.f;
        const float* row = memory + (size_t)i * MW;
#pragma unroll
        for (int m = 0; m < MW; m++) s += row[m] * row[m];
        sbn[i] = sqrtf(s);
    }
    const float bk_r = (tid < MW) ? b_key[tid] : 0.f;
    __syncthreads();

    for (int t = 0; t < T_SZ; t++) {
        cpa16(spre_u + tid * 16,
              g_pre + (size_t)(t * 64 + b) * NH + rowoff + tid * 4);
        CP_COMMIT;

        float part[MW];
#pragma unroll
        for (int j = 0; j < MW; j++) part[j] = 0.f;
        for (int r = tid; r < 1024; r += 256) {
            float hv = sh[r];
            const float* kr = &skey[r * 21];
#pragma unroll
            for (int j = 0; j < MW; j++) part[j] += hv * kr[j];
        }
#pragma unroll
        for (int j = 0; j < MW; j++) {
#pragma unroll
            for (int o = 16; o > 0; o >>= 1)
                part[j] += __shfl_xor_sync(0xffffffffu, part[j], o);
        }
        if (lane == 0) {
#pragma unroll
            for (int j = 0; j < MW; j++) sred[warp * MW + j] = part[j];
        }
        __syncthreads();  // sred ready

        if (warp == 0) {
            const int bkx = t & (MBK - 1);
            const float* bank = memory + (size_t)bkx * MN * MW;
            float kv = 0.f;
            if (lane < MW) {
#pragma unroll
                for (int w = 0; w < 8; w++) kv += sred[w * MW + lane];
                ((volatile float*)g_kpart)[self * MW + lane] = kv;
            }
            __syncwarp();
            __threadfence();
            if (lane == 0) {
                ((volatile int*)g_kflag)[self] = t + 1;
                volatile int* kf = g_kflag;
                while (kf[peer] < t + 1) __nanosleep(128);
            }
            __syncwarp();
            __threadfence();
            float kfull = 0.f;
            if (lane < MW) {
                kfull = kv + ((volatile float*)g_kpart)[peer * MW + lane] + bk_r;
                skv[lane] = kfull;
            }
            float sq = kfull * kfull;
#pragma unroll
            for (int o = 16; o > 0; o >>= 1)
                sq += __shfl_xor_sync(0xffffffffu, sq, o);
            const float kn = sqrtf(sq);
            __syncwarp();

            float pv[4];
#pragma unroll
            for (int q = 0; q < 4; q++) {
                const int row = q * 32 + lane;
                const float4* bn = (const float4*)(bank + (size_t)row * MW);
                float d = 0.f;
#pragma unroll
                for (int j4 = 0; j4 < 5; j4++) {
                    float4 w = __ldg(&bn[j4]);
                    d += skv[j4 * 4 + 0] * w.x + skv[j4 * 4 + 1] * w.y +
                         skv[j4 * 4 + 2] * w.z + skv[j4 * 4 + 3] * w.w;
                }
                pv[q] = d / (kn * sbn[bkx * MN + row] + 1e-8f);
            }
            float mx = fmaxf(fmaxf(pv[0], pv[1]), fmaxf(pv[2], pv[3]));
#pragma unroll
            for (int o = 16; o > 0; o >>= 1)
                mx = fmaxf(mx, __shfl_xor_sync(0xffffffffu, mx, o));
            float e[4], s = 0.f;
#pragma unroll
            for (int q = 0; q < 4; q++) {
                e[q] = expf(pv[q] - mx);
                s += e[q];
            }
#pragma unroll
            for (int o = 16; o > 0; o >>= 1)
                s += __shfl_xor_sync(0xffffffffu, s, o);
            const float inv = 1.f / s;
#pragma unroll
            for (int q = 0; q < 4; q++) sprob[q * 32 + lane] = e[q] * inv;
            __syncwarp();
            if (lane < MW) {
                float a = 0.f;
#pragma unroll 8
                for (int n = 0; n < MN; n++)
                    a += sprob[n] * __ldg(bank + (size_t)n * MW + lane);
                sr[lane] = a;
            }
        }
        __syncthreads();  // sr ready

        {
            cp_wait0();
            float4 v = ((const float4*)spre)[tid];
#pragma unroll
            for (int m = 0; m < MW; m++) {
                float rm = sr[m];
                float4 w = __ldg(
                    &((const float4*)(W_read + (size_t)m * NH + rowoff))[tid]);
                v.x += rm * w.x; v.y += rm * w.y;
                v.z += rm * w.z; v.w += rm * w.w;
            }
            v.x = fmaxf(v.x, 0.f); v.y = fmaxf(v.y, 0.f);
            v.z = fmaxf(v.z, 0.f); v.w = fmaxf(v.w, 0.f);
            ((float4*)sh)[tid] = v;

            const size_t rowb = (size_t)(t * 64 + b) * KW;
            __nv_bfloat16 hx = __float2bfloat16(v.x), hy = __float2bfloat16(v.y);
            __nv_bfloat16 hz = __float2bfloat16(v.z), hw = __float2bfloat16(v.w);
            __nv_bfloat162* ph = (__nv_bfloat162*)(g_Ah + rowb + rowoff);
            ph[2 * tid] = __halves2bfloat162(hx, hy);
            ph[2 * tid + 1] = __halves2bfloat162(hz, hw);
            __nv_bfloat162* pl = (__nv_bfloat162*)(g_Ah + rowb + 2048 + rowoff);
            pl[2 * tid] = __halves2bfloat162(
                __float2bfloat16(v.x - __bfloat162float(hx)),
                __float2bfloat16(v.y - __bfloat162float(hy)));
            pl[2 * tid + 1] = __halves2bfloat162(
                __float2bfloat16(v.z - __bfloat162float(hz)),
                __float2bfloat16(v.w - __bfloat162float(hw)));
        }
        __threadfence();
        __syncthreads();
        if (tid == 0) atomicAdd(&g_prog[t], 1);
    }
}

// ---------------- fused: recur(128) + gemm1(512) ------------------------------
__global__ void __launch_bounds__(256, 2)
fused2(const float* __restrict__ h0, const float* __restrict__ b_key,
       const float* __restrict__ W_read, const float* __restrict__ memory,
       const float* __restrict__ W_key, const float* __restrict__ b_out,
       float* __restrict__ out) {
    extern __shared__ char dsm[];
    const int bid = blockIdx.x;
    if (bid < 128) {
        recur_half(dsm, bid >> 1, bid & 1, h0, b_key, W_read, memory, W_key);
    } else {
        gemm_body<1>(dsm, bid - 128, g_Ah, g_B1, b_out, out);
    }
}

// ---------------- host -------------------------------------------------------
extern "C" void kernel_launch(void* const* d_in, const int* in_sizes, int n_in,
                              void* d_out, int out_size) {
    const float* x      = (const float*)d_in[0];
    const float* h0     = (const float*)d_in[1];
    const float* W_in   = (const float*)d_in[2];
    const float* b_in   = (const float*)d_in[3];
    const float* W_read = (const float*)d_in[4];
    const float* b_read = (const float*)d_in[5];
    const float* W_out  = (const float*)d_in[6];
    const float* b_out  = (const float*)d_in[7];
    const float* W_key  = (const float*)d_in[8];
    const float* b_key  = (const float*)d_in[9];
    const float* memory = (const float*)d_in[10];
    float* out = (float*)d_out;

    cudaFuncSetAttribute(gemm0_k, cudaFuncAttributeMaxDynamicSharedMemorySize,
                         GEMM_SMEM);
    cudaFuncSetAttribute(fused2, cudaFuncAttributeMaxDynamicSharedMemorySize,
                         GEMM_SMEM);

    __nv_bfloat16 *B0, *B1;
    cudaGetSymbolAddress((void**)&B0, g_B0);
    cudaGetSymbolAddress((void**)&B1, g_B1);

    init_flags<<<1, 256>>>();
    conv_x<<<(M_ROWS * NI / 4 + 255) / 256, 256>>>((const float4*)x);
    trans_split<<<dim3(64, 64), dim3(32, 8)>>>(W_in, B0);
    trans_split<<<dim3(64, 64), dim3(32, 8)>>>(W_out, B1);
    bias_comb<<<4, 512>>>(b_in, b_read);

    gemm0_k<<<512, 256, GEMM_SMEM>>>();
    fused2<<<640, 256, GEMM_SMEM>>>(h0, b_key, W_read, memory, W_key, b_out, out);
}

// round 10
// speedup vs baseline: 1.5171x; 1.5171x over previous
#include <cuda_runtime.h>
#include <cuda_bf16.h>
#include <math.h>
#include <stdint.h>

#define B_SZ 64
#define T_SZ 64
#define NI 2048
#define NH 2048
#define MBK 4
#define MN 128
#define MW 20
#define M_ROWS 4096
#define KW 4096   // compact split width [hi | lo]
#define KX 6144   // logical K (3 terms x 2048)

// ---------------- device scratch (t-major rows: r = t*64 + b) ----------------
__device__ float g_pre[(size_t)M_ROWS * NH];
__device__ float g_bpre[NH];
__device__ __nv_bfloat16 g_Ax[(size_t)M_ROWS * KW];   // x split
__device__ __nv_bfloat16 g_Ah[(size_t)M_ROWS * KW];   // H split
__device__ __nv_bfloat16 g_B0[(size_t)NH * KW];       // W_in^T  [hi|lo]
__device__ __nv_bfloat16 g_B1[(size_t)NH * KW];       // W_out^T [hi|lo]

// ---------------- helpers ----------------------------------------------------
__device__ __forceinline__ uint32_t s2u(const void* p) {
    uint32_t r;
    asm("{ .reg .u64 t; cvta.to.shared.u64 t, %1; cvt.u32.u64 %0, t; }"
        : "=r"(r) : "l"(p));
    return r;
}
#define SWZ(x) ((x) ^ (((x) >> 3) & 0x70))
__device__ __forceinline__ void cpa16(uint32_t s, const void* g) {
    asm volatile("cp.async.cg.shared.global [%0], [%1], 16;" :: "r"(s), "l"(g)
                 : "memory");
}
#define CP_COMMIT asm volatile("cp.async.commit_group;" ::: "memory")
__device__ __forceinline__ void cp_wait1() {
    asm volatile("cp.async.wait_group 1;" ::: "memory");
}
__device__ __forceinline__ void cp_wait0() {
    asm volatile("cp.async.wait_group 0;" ::: "memory");
}
__device__ __forceinline__ void ldsm4(uint32_t* r, uint32_t a) {
    asm volatile("ldmatrix.sync.aligned.m8n8.x4.shared.b16 {%0,%1,%2,%3}, [%4];"
                 : "=r"(r[0]), "=r"(r[1]), "=r"(r[2]), "=r"(r[3]) : "r"(a));
}
__device__ __forceinline__ void mma16816(float* c, const uint32_t* a,
                                         const uint32_t* b) {
    asm volatile(
        "mma.sync.aligned.m16n8k16.row.col.f32.bf16.bf16.f32 "
        "{%0,%1,%2,%3}, {%4,%5,%6,%7}, {%8,%9}, {%0,%1,%2,%3};"
        : "+f"(c[0]), "+f"(c[1]), "+f"(c[2]), "+f"(c[3])
        : "r"(a[0]), "r"(a[1]), "r"(a[2]), "r"(a[3]), "r"(b[0]), "r"(b[1]));
}

// ---------------- small prep kernels -----------------------------------------
__global__ void conv_x(const float4* __restrict__ x4) {
    int i = blockIdx.x * 256 + threadIdx.x;
    if (i >= M_ROWS * NI / 4) return;
    int row = i >> 9, c4 = i & 511;          // input row = b*64 + t
    int b = row >> 6, t = row & 63;
    int orow = t * 64 + b;                   // t-major
    float4 v = x4[i];
    __nv_bfloat16 hx = __float2bfloat16(v.x), hy = __float2bfloat16(v.y);
    __nv_bfloat16 hz = __float2bfloat16(v.z), hw = __float2bfloat16(v.w);
    __nv_bfloat162* p = (__nv_bfloat162*)(g_Ax + (size_t)orow * KW);
    p[2 * c4] = __halves2bfloat162(hx, hy);
    p[2 * c4 + 1] = __halves2bfloat162(hz, hw);
    p[1024 + 2 * c4] = __halves2bfloat162(
        __float2bfloat16(v.x - __bfloat162float(hx)),
        __float2bfloat16(v.y - __bfloat162float(hy)));
    p[1024 + 2 * c4 + 1] = __halves2bfloat162(
        __float2bfloat16(v.z - __bfloat162float(hz)),
        __float2bfloat16(v.w - __bfloat162float(hw)));
}

// z=0: W_in -> g_B0, z=1: W_out -> g_B1
__global__ void trans_split(const float* __restrict__ W0,
                            const float* __restrict__ W1) {
    __shared__ float s[32][33];
    const float* W = blockIdx.z ? W1 : W0;
    __nv_bfloat16* T = blockIdx.z ? g_B1 : g_B0;
    int n0 = blockIdx.x * 32, k0 = blockIdx.y * 32;
    int tx = threadIdx.x, ty = threadIdx.y;
#pragma unroll
    for (int i = 0; i < 32; i += 8)
        s[ty + i][tx] = W[(size_t)(k0 + ty + i) * NH + n0 + tx];
    __syncthreads();
#pragma unroll
    for (int i = 0; i < 32; i += 8) {
        float v = s[tx][ty + i];
        __nv_bfloat16 h = __float2bfloat16(v);
        __nv_bfloat16 l = __float2bfloat16(v - __bfloat162float(h));
        size_t o = (size_t)(n0 + ty + i) * KW + k0 + tx;
        T[o] = h;
        T[o + 2048] = l;
    }
}

__global__ void bias_comb(const float* __restrict__ a,
                          const float* __restrict__ b) {
    int i = blockIdx.x * 512 + threadIdx.x;
    if (i < NH) g_bpre[i] = a[i] + b[i];
}

// ---------------- GEMM ------------------------------------------------------
#define BM 128
#define BN 128
#define BK 64
#define STG 3
#define STAGE_B 32768
#define NT (KX / BK)  // 96
#define GEMM_SMEM (STG * STAGE_B + 1024)  // 99328

template <int MODE>  // 0: C=g_pre (t-major) | 1: C=out remap+clamp
__device__ void gemm_body(char* dsm, int cta,
                          const __nv_bfloat16* __restrict__ Ag,
                          const __nv_bfloat16* __restrict__ Bg,
                          const float* __restrict__ bias,
                          float* __restrict__ C) {
    const int by = cta >> 4, bx = cta & 15;
    const int tid = threadIdx.x, lane = tid & 31, wid = tid >> 5;
    const int wm = wid & 1, wn = wid >> 1;

    uint32_t base = (s2u(dsm) + 1023u) & ~1023u;
    const __nv_bfloat16* Abase = Ag + (size_t)(by * BM + (tid >> 3)) * KW +
                                 (tid & 7) * 8;
    const __nv_bfloat16* Bbase = Bg + (size_t)(bx * BN + (tid >> 3)) * KW +
                                 (tid & 7) * 8;

    float acc[4][4][4];
#pragma unroll
    for (int m = 0; m < 4; m++)
#pragma unroll
        for (int n = 0; n < 4; n++)
#pragma unroll
            for (int q = 0; q < 4; q++) acc[m][n][q] = 0.f;

    uint32_t stoff[4];
#pragma unroll
    for (int u = 0; u < 4; u++) {
        int unit = tid + 256 * u;
        stoff[u] = SWZ((uint32_t)((unit >> 3) * 128 + (unit & 7) * 16));
    }

    auto load_stage = [&](int s, int ks) {
        int ka = ((ks & 31) + ((ks >= 64) ? 32 : 0)) * 64;
        int kb = ((ks & 31) + (((ks >> 5) == 1) ? 32 : 0)) * 64;
        uint32_t sb = base + s * STAGE_B;
#pragma unroll
        for (int u = 0; u < 4; u++)
            cpa16(sb + stoff[u], Abase + (size_t)(32 * u) * KW + ka);
#pragma unroll
        for (int u = 0; u < 4; u++)
            cpa16(sb + 16384 + stoff[u], Bbase + (size_t)(32 * u) * KW + kb);
    };

    load_stage(0, 0);
    CP_COMMIT;
    load_stage(1, 1);
    CP_COMMIT;

    uint32_t aoff[4], boff[2];
#pragma unroll
    for (int mt = 0; mt < 4; mt++)
        aoff[mt] = (uint32_t)((wm * 64 + mt * 16 + (lane & 15)) * 128 +
                              (lane >> 4) * 16);
#pragma unroll
    for (int p = 0; p < 2; p++)
        boff[p] = (uint32_t)((wn * 32 + p * 16 + (lane & 15)) * 128 +
                             (lane >> 4) * 16);

    for (int ks = 0; ks < NT; ks++) {
        if (ks < NT - 1) cp_wait1();
        else cp_wait0();
        __syncthreads();
        if (ks + 2 < NT) {
            load_stage((ks + 2) % STG, ks + 2);
            CP_COMMIT;
        }
        const uint32_t sa = base + (ks % STG) * STAGE_B;
        const uint32_t sb = sa + 16384;
#pragma unroll
        for (int k16 = 0; k16 < 4; k16++) {
            uint32_t aF[4][4], bF[4][2];
#pragma unroll
            for (int mt = 0; mt < 4; mt++)
                ldsm4(aF[mt], sa + SWZ(aoff[mt] + k16 * 32));
#pragma unroll
            for (int p = 0; p < 2; p++) {
                uint32_t t[4];
                ldsm4(t, sb + SWZ(boff[p] + k16 * 32));
                bF[2 * p][0] = t[0];
                bF[2 * p][1] = t[2];
                bF[2 * p + 1][0] = t[1];
                bF[2 * p + 1][1] = t[3];
            }
#pragma unroll
            for (int mt = 0; mt < 4; mt++)
#pragma unroll
                for (int nt = 0; nt < 4; nt++)
                    mma16816(acc[mt][nt], aF[mt], bF[nt]);
        }
        __syncthreads();
    }

    const int g = lane >> 2, t4 = lane & 3;
#pragma unroll
    for (int mt = 0; mt < 4; mt++) {
        const int r0 = by * BM + wm * 64 + mt * 16 + g;
        size_t rowbase, rowbase8;
        if (MODE == 0) {
            rowbase = (size_t)r0 * NH;
            rowbase8 = (size_t)(r0 + 8) * NH;
        } else {
            rowbase = (size_t)((r0 & 63) * 64 + (r0 >> 6)) * NH;
            rowbase8 = (size_t)(((r0 + 8) & 63) * 64 + ((r0 + 8) >> 6)) * NH;
        }
#pragma unroll
        for (int nt = 0; nt < 4; nt++) {
            const int c0 = bx * BN + wn * 32 + nt * 8 + t4 * 2;
            float2 bb2 = *(const float2*)&bias[c0];
            float v0 = acc[mt][nt][0] + bb2.x, v1 = acc[mt][nt][1] + bb2.y;
            float v2 = acc[mt][nt][2] + bb2.x, v3 = acc[mt][nt][3] + bb2.y;
            if (MODE == 1) {
                v0 = fminf(fmaxf(v0, 0.f), 1.f);
                v1 = fminf(fmaxf(v1, 0.f), 1.f);
                v2 = fminf(fmaxf(v2, 0.f), 1.f);
                v3 = fminf(fmaxf(v3, 0.f), 1.f);
            }
            float2 w0 = {v0, v1}, w1 = {v2, v3};
            *(float2*)&C[rowbase + c0] = w0;
            *(float2*)&C[rowbase8 + c0] = w1;
        }
    }
}

__global__ void __launch_bounds__(256, 2) gemm0_k() {
    extern __shared__ char dsm[];
    gemm_body<0>(dsm, blockIdx.x, g_Ax, g_B0, g_bpre, g_pre);
}
__global__ void __launch_bounds__(256, 2) gemm1_k(const float* __restrict__ b_out,
                                                  float* __restrict__ out) {
    extern __shared__ char dsm[];
    gemm_body<1>(dsm, blockIdx.x, g_Ah, g_B1, b_out, out);
}

// ---------------- recurrence: one block per batch row, 512 threads -----------
// smem floats (j-major W_key):
//  skey [20][2048] | sh 2048 | spre 2048 | sbn 512 | part [20][512] |
//  ssim 128 | sprob 128 | sk 24 | sr 24
#define RSM_KEY 0
#define RSM_H (MW * NH)                 // 40960
#define RSM_PRE (RSM_H + NH)            // +2048
#define RSM_BN (RSM_PRE + NH)           // +2048
#define RSM_PART (RSM_BN + 512)
#define RSM_SIM (RSM_PART + MW * 512)   // +10240
#define RSM_PROB (RSM_SIM + 128)
#define RSM_K (RSM_PROB + 128)
#define RSM_R (RSM_K + 24)
#define RECUR_SMEM ((RSM_R + 24) * 4)   // 224,544 B

__global__ void __launch_bounds__(512, 1)
recur_k(const float* __restrict__ h0, const float* __restrict__ b_key,
        const float* __restrict__ W_read, const float* __restrict__ memory,
        const float* __restrict__ W_key) {
    extern __shared__ float rs[];
    float* skey = rs + RSM_KEY;
    float* sh = rs + RSM_H;
    float* spre = rs + RSM_PRE;
    float* sbn = rs + RSM_BN;
    float* spart = rs + RSM_PART;
    float* ssim = rs + RSM_SIM;
    float* sprob = rs + RSM_PROB;
    float* sk = rs + RSM_K;
    float* sr = rs + RSM_R;
    const uint32_t spre_u = s2u(spre);

    const int b = blockIdx.x;
    const int tid = threadIdx.x;
    const int lane = tid & 31, warp = tid >> 5;

    for (int i = tid; i < NH; i += 512) sh[i] = h0[(size_t)b * NH + i];
    // W_key j-major: skey[j][r]
    for (int r = tid; r < NH; r += 512) {
        const float* kr = W_key + (size_t)r * MW;
#pragma unroll
        for (int j = 0; j < MW; j++) skey[j * NH + r] = kr[j];
    }
    for (int i = tid; i < MBK * MN; i += 512) {
        float s = 0.f;
        const float* row = memory + (size_t)i * MW;
#pragma unroll
        for (int m = 0; m < MW; m++) s += row[m] * row[m];
        sbn[i] = sqrtf(s);
    }
    __syncthreads();

    for (int t = 0; t < T_SZ; t++) {
        // prefetch this step's pre row
        cpa16(spre_u + tid * 16,
              g_pre + (size_t)(t * 64 + b) * NH + tid * 4);
        CP_COMMIT;

        // ---- k partials: rows r = tid + 512m (immediate-offset LDS) ----
        float part[MW];
#pragma unroll
        for (int j = 0; j < MW; j++) part[j] = 0.f;
#pragma unroll
        for (int m = 0; m < 4; m++) {
            const int r = tid + 512 * m;
            const float hv = sh[r];
            const float* kp = skey + r;
#pragma unroll
            for (int j = 0; j < MW; j++) part[j] += hv * kp[j * NH];
        }
#pragma unroll
        for (int j = 0; j < MW; j++) spart[j * 512 + tid] = part[j];
        __syncthreads();  // bar1: partials ready

        // ---- stage2 reduce: warp w handles j = w, and j = w+16 if w<4 ----
        {
            int jj = warp;
#pragma unroll
            for (int round = 0; round < 2; round++) {
                if (jj < MW) {
                    const float* pp = spart + jj * 512 + lane;
                    float s = 0.f;
#pragma unroll
                    for (int i = 0; i < 16; i++) s += pp[32 * i];
#pragma unroll
                    for (int o = 16; o > 0; o >>= 1)
                        s += __shfl_xor_sync(0xffffffffu, s, o);
                    if (lane == 0) sk[jj] = s + b_key[jj];
                }
                jj = warp + 16;
            }
        }
        __syncthreads();  // bar2: k ready

        // ---- sim by warps 0..3 (32 rows each) ----
        const int bkx = t & (MBK - 1);
        const float* bank = memory + (size_t)bkx * MN * MW;
        if (warp < 4) {
            float kv = (lane < MW) ? sk[lane] : 0.f;
            float sq = kv * kv;
#pragma unroll
            for (int o = 16; o > 0; o >>= 1)
                sq += __shfl_xor_sync(0xffffffffu, sq, o);
            const float kn = sqrtf(sq);
            const int row = warp * 32 + lane;
            const float4* bn = (const float4*)(bank + (size_t)row * MW);
            float d = 0.f;
#pragma unroll
            for (int j4 = 0; j4 < 5; j4++) {
                float4 w = __ldg(&bn[j4]);
                d += sk[j4 * 4 + 0] * w.x + sk[j4 * 4 + 1] * w.y +
                     sk[j4 * 4 + 2] * w.z + sk[j4 * 4 + 3] * w.w;
            }
            ssim[row] = d / (kn * sbn[bkx * MN + row] + 1e-8f);
        }
        __syncthreads();  // bar3: sim ready

        // ---- softmax over 128 (warp 0) ----
        if (warp == 0) {
            float v[4];
#pragma unroll
            for (int q = 0; q < 4; q++) v[q] = ssim[q * 32 + lane];
            float mx = fmaxf(fmaxf(v[0], v[1]), fmaxf(v[2], v[3]));
#pragma unroll
            for (int o = 16; o > 0; o >>= 1)
                mx = fmaxf(mx, __shfl_xor_sync(0xffffffffu, mx, o));
            float e[4], s = 0.f;
#pragma unroll
            for (int q = 0; q < 4; q++) {
                e[q] = expf(v[q] - mx);
                s += e[q];
            }
#pragma unroll
            for (int o = 16; o > 0; o >>= 1)
                s += __shfl_xor_sync(0xffffffffu, s, o);
            const float inv = 1.f / s;
#pragma unroll
            for (int q = 0; q < 4; q++) sprob[q * 32 + lane] = e[q] * inv;
        }
        __syncthreads();  // bar4: prob ready

        // ---- r by warps 0..3: warp w handles j = w*5..w*5+4 ----
        if (warp < 4) {
#pragma unroll
            for (int q = 0; q < 5; q++) {
                const int j = warp * 5 + q;
                float a = 0.f;
#pragma unroll
                for (int m = 0; m < 4; m++) {
                    const int n = lane + 32 * m;
                    a += sprob[n] * __ldg(bank + (size_t)n * MW + j);
                }
#pragma unroll
                for (int o = 16; o > 0; o >>= 1)
                    a += __shfl_xor_sync(0xffffffffu, a, o);
                if (lane == 0) sr[j] = a;
            }
        }
        __syncthreads();  // bar5: r ready

        // ---- epilogue: h_new = relu(pre(+biases) + r @ W_read) ----
        {
            cp_wait0();
            float4 v = ((const float4*)spre)[tid];
#pragma unroll
            for (int m = 0; m < MW; m++) {
                float rm = sr[m];
                float4 w = __ldg(&((const float4*)W_read)[m * (NH / 4) + tid]);
                v.x += rm * w.x; v.y += rm * w.y;
                v.z += rm * w.z; v.w += rm * w.w;
            }
            v.x = fmaxf(v.x, 0.f); v.y = fmaxf(v.y, 0.f);
            v.z = fmaxf(v.z, 0.f); v.w = fmaxf(v.w, 0.f);
            ((float4*)sh)[tid] = v;

            const size_t rowb = (size_t)(t * 64 + b) * KW;
            __nv_bfloat16 hx = __float2bfloat16(v.x), hy = __float2bfloat16(v.y);
            __nv_bfloat16 hz = __float2bfloat16(v.z), hw = __float2bfloat16(v.w);
            __nv_bfloat162* ph = (__nv_bfloat162*)(g_Ah + rowb);
            ph[2 * tid] = __halves2bfloat162(hx, hy);
            ph[2 * tid + 1] = __halves2bfloat162(hz, hw);
            __nv_bfloat162* pl = (__nv_bfloat162*)(g_Ah + rowb + 2048);
            pl[2 * tid] = __halves2bfloat162(
                __float2bfloat16(v.x - __bfloat162float(hx)),
                __float2bfloat16(v.y - __bfloat162float(hy)));
            pl[2 * tid + 1] = __halves2bfloat162(
                __float2bfloat16(v.z - __bfloat162float(hz)),
                __float2bfloat16(v.w - __bfloat162float(hw)));
        }
        __syncthreads();  // bar6: sh ready for next step
    }
}

// ---------------- host -------------------------------------------------------
extern "C" void kernel_launch(void* const* d_in, const int* in_sizes, int n_in,
                              void* d_out, int out_size) {
    const float* x      = (const float*)d_in[0];
    const float* h0     = (const float*)d_in[1];
    const float* W_in   = (const float*)d_in[2];
    const float* b_in   = (const float*)d_in[3];
    const float* W_read = (const float*)d_in[4];
    const float* b_read = (const float*)d_in[5];
    const float* W_out  = (const float*)d_in[6];
    const float* b_out  = (const float*)d_in[7];
    const float* W_key  = (const float*)d_in[8];
    const float* b_key  = (const float*)d_in[9];
    const float* memory = (const float*)d_in[10];
    float* out = (float*)d_out;

    cudaFuncSetAttribute(gemm0_k, cudaFuncAttributeMaxDynamicSharedMemorySize,
                         GEMM_SMEM);
    cudaFuncSetAttribute(gemm1_k, cudaFuncAttributeMaxDynamicSharedMemorySize,
                         GEMM_SMEM);
    cudaFuncSetAttribute(recur_k, cudaFuncAttributeMaxDynamicSharedMemorySize,
                         RECUR_SMEM);

    conv_x<<<(M_ROWS * NI / 4 + 255) / 256, 256>>>((const float4*)x);
    trans_split<<<dim3(64, 64, 2), dim3(32, 8)>>>(W_in, W_out);
    bias_comb<<<4, 512>>>(b_in, b_read);

    gemm0_k<<<512, 256, GEMM_SMEM>>>();
    recur_k<<<B_SZ, 512, RECUR_SMEM>>>(h0, b_key, W_read, memory, W_key);
    gemm1_k<<<512, 256, GEMM_SMEM>>>(b_out, out);
}